// round 9
// baseline (speedup 1.0000x reference)
#include <cuda_runtime.h>
#include <math.h>

#define ULL unsigned long long

// ---------------- packed f32x2 helpers (sm_103a) ----------------
__device__ __forceinline__ ULL pack2(float x) {
    ULL d; asm("mov.b64 %0, {%1, %1};" : "=l"(d) : "f"(x)); return d;
}
__device__ __forceinline__ ULL fma2(ULL a, ULL b, ULL c) {
    ULL d; asm("fma.rn.f32x2 %0, %1, %2, %3;" : "=l"(d) : "l"(a), "l"(b), "l"(c)); return d;
}
__device__ __forceinline__ ULL add2(ULL a, ULL b) {
    ULL d; asm("add.rn.f32x2 %0, %1, %2;" : "=l"(d) : "l"(a), "l"(b)); return d;
}
__device__ __forceinline__ void unpack2(ULL v, float& lo, float& hi) {
    asm("mov.b64 {%0, %1}, %2;" : "=f"(lo), "=f"(hi) : "l"(v));
}

// mish(x) = x * tanh(softplus(x)) = x * (e^2x + 2e^x) / (e^2x + 2e^x + 2)
__device__ __forceinline__ float mish_f(float v) {
    if (v > 20.f) return v;
    float e = expf(v);
    float n = e * e + 2.f * e;
    return v * (n / (n + 2.f));
}

constexpr int HID  = 256;
constexpr int ADIM = 16;
constexpr int SDIM = 64;
constexpr int TDIM = 32;
constexpr int TS   = 100;
constexpr int MT   = 16;    // batch rows per CTA
constexpr int HS   = 260;   // padded stride for activation tiles

struct __align__(16) Smem {
    float r1[TS], r2[TS], c1[TS], c2[TS], stdv[TS];   // schedule
    float x[MT * ADIM];
    float hA[MT * HS];
    float hB[MT * HS];
    float S[MT * HID];          // state @ W1_state + b1 (step-invariant)
    float W1x[ADIM * HID];      // W1 rows 0..15   (x part)
    float W1t[TDIM * HID];      // W1 rows 16..47  (time part)
    float TW1[TDIM * HID];      // time_W1
    float TW2[HID * TDIM];      // time_W2
    float W4T[ADIM * HS];       // W4 transposed, padded stride
    float b2[HID], b3[HID], b4[ADIM], tb1[HID], tb2[TDIM];
    float emb[TDIM], t1[HID], tpart[HID], temb[TDIM], tcon[HID];
};

// C[16 x 256] = mish( A[16 x 256] @ W[256 x 256] + bias ), W streamed from L2,
// packed f32x2 accumulation, depth-8 software pipeline on the weight loads.
__device__ __forceinline__ void gemm_hidden(const float* __restrict__ Wg,
                                            const float* bsm,
                                            const float* src, float* dst,
                                            int tx, int ty) {
    ULL acc[4][2];
    {
        ulonglong2 bv = *(reinterpret_cast<const ulonglong2*>(bsm) + tx);
        #pragma unroll
        for (int r = 0; r < 4; r++) { acc[r][0] = bv.x; acc[r][1] = bv.y; }
    }
    const ulonglong2* wp = reinterpret_cast<const ulonglong2*>(Wg) + tx;
    ulonglong2 cur[8];
    #pragma unroll
    for (int u = 0; u < 8; u++) cur[u] = __ldg(wp + u * 64);
    const float* a0 = src + (ty << 2) * HS;

    #pragma unroll 1
    for (int kk = 0; kk < HID; kk += 8) {
        ulonglong2 nxt[8];
        #pragma unroll
        for (int u = 0; u < 8; u++) {
            int kl = kk + 8 + u;
            kl = kl > HID - 1 ? HID - 1 : kl;   // safe clamp (last iter wasted)
            nxt[u] = __ldg(wp + kl * 64);
        }
        #pragma unroll
        for (int r = 0; r < 4; r++) {
            float4 A0 = *reinterpret_cast<const float4*>(a0 + r * HS + kk);
            float4 A1 = *reinterpret_cast<const float4*>(a0 + r * HS + kk + 4);
            float av[8] = {A0.x, A0.y, A0.z, A0.w, A1.x, A1.y, A1.z, A1.w};
            #pragma unroll
            for (int u = 0; u < 8; u++) {
                ULL a2 = pack2(av[u]);
                acc[r][0] = fma2(a2, cur[u].x, acc[r][0]);
                acc[r][1] = fma2(a2, cur[u].y, acc[r][1]);
            }
        }
        #pragma unroll
        for (int u = 0; u < 8; u++) cur[u] = nxt[u];
    }
    #pragma unroll
    for (int r = 0; r < 4; r++) {
        float a, b, c, d;
        unpack2(acc[r][0], a, b);
        unpack2(acc[r][1], c, d);
        *reinterpret_cast<float4*>(dst + (4 * ty + r) * HS + 4 * tx) =
            make_float4(mish_f(a), mish_f(b), mish_f(c), mish_f(d));
    }
}

__global__ __launch_bounds__(256, 1)
void diffusion_kernel(const float* __restrict__ state,
                      const float* __restrict__ x_init,
                      const float* __restrict__ noise,
                      const float* __restrict__ tW1g, const float* __restrict__ tb1g,
                      const float* __restrict__ tW2g, const float* __restrict__ tb2g,
                      const float* __restrict__ W1,   const float* __restrict__ b1,
                      const float* __restrict__ W2,   const float* __restrict__ b2g,
                      const float* __restrict__ W3,   const float* __restrict__ b3g,
                      const float* __restrict__ W4,   const float* __restrict__ b4g,
                      float* __restrict__ out) {
    extern __shared__ char smem_raw[];
    Smem* s = reinterpret_cast<Smem*>(smem_raw);
    const int tid = threadIdx.x;
    const int tx = tid & 63, ty = tid >> 6;     // 64 col-groups x 4 row-groups
    const int row0 = blockIdx.x * MT;
    const int um = tid >> 4, uj = tid & 15;     // update/GEMM4 mapping

    // ---- cache weights / biases in smem ----
    for (int i = tid; i < ADIM * HID; i += 256) s->W1x[i] = W1[i];
    for (int i = tid; i < TDIM * HID; i += 256) s->W1t[i] = W1[ADIM * HID + i];
    for (int i = tid; i < TDIM * HID; i += 256) s->TW1[i] = tW1g[i];
    for (int i = tid; i < HID * TDIM; i += 256) s->TW2[i] = tW2g[i];
    for (int i = tid; i < HID; i += 256) { s->b2[i] = b2g[i]; s->b3[i] = b3g[i]; s->tb1[i] = tb1g[i]; }
    if (tid < ADIM) s->b4[tid] = b4g[tid];
    if (tid >= 32 && tid < 64) s->tb2[tid - 32] = tb2g[tid - 32];
    for (int i = tid; i < HID * ADIM; i += 256) {  // W4 [256x16] -> W4T [16][260]
        int k = i >> 4, j = i & 15;
        s->W4T[j * HS + k] = W4[i];
    }
    s->x[tid] = x_init[row0 * ADIM + tid];
    for (int i = tid; i < MT * SDIM; i += 256) s->hB[i] = state[row0 * SDIM + i]; // scratch

    // ---- schedule via closed-form cumprod: ac[n] = exp(sum of log-alphas) ----
    if (tid < TS) {
        const double T = 100.0, bmax = 10.0, bmin = 0.1;
        double n1 = (double)(tid + 1), n0 = (double)tid;
        double g1 = -bmin * n1 / T - 0.5 * (bmax - bmin) * n1 * n1 / (T * T);
        double g0 = -bmin * n0 / T - 0.5 * (bmax - bmin) * n0 * n0 / (T * T);
        double ac = exp(g1), acp = exp(g0);
        double alpha = exp(g1 - g0);
        double beta = 1.0 - alpha;
        s->r1[tid] = (float)sqrt(1.0 / ac);
        s->r2[tid] = (float)sqrt(1.0 / ac - 1.0);
        s->c1[tid] = (float)(beta * sqrt(acp) / (1.0 - ac));
        s->c2[tid] = (float)((1.0 - acp) * sqrt(alpha) / (1.0 - ac));
        double v = beta * (1.0 - acp) / (1.0 - ac);
        if (v < 1e-20) v = 1e-20;
        s->stdv[tid] = expf(0.5f * (float)log(v));
    }
    __syncthreads();

    // ---- S = state @ W1[48:112] + b1  (once) ----
    {
        ULL acc[4][2];
        ulonglong2 bv = __ldg(reinterpret_cast<const ulonglong2*>(b1) + tx);
        #pragma unroll
        for (int r = 0; r < 4; r++) { acc[r][0] = bv.x; acc[r][1] = bv.y; }
        const ulonglong2* wp = reinterpret_cast<const ulonglong2*>(W1 + (ADIM + TDIM) * HID) + tx;
        const float* a0 = s->hB + (ty * 4) * SDIM;
        for (int k = 0; k < SDIM; k++) {
            ulonglong2 w = __ldg(wp + k * 64);
            #pragma unroll
            for (int r = 0; r < 4; r++) {
                ULL a2 = pack2(a0[r * SDIM + k]);
                acc[r][0] = fma2(a2, w.x, acc[r][0]);
                acc[r][1] = fma2(a2, w.y, acc[r][1]);
            }
        }
        #pragma unroll
        for (int r = 0; r < 4; r++) {
            float a, b, c, d;
            unpack2(acc[r][0], a, b);
            unpack2(acc[r][1], c, d);
            *reinterpret_cast<float4*>(s->S + (4 * ty + r) * HID + 4 * tx) = make_float4(a, b, c, d);
        }
    }
    __syncthreads();

    // ---- 100-step reverse diffusion ----
    for (int sstep = 0; sstep < TS; sstep++) {
        int i = TS - 1 - sstep;

        // sinusoidal embedding (t is a scalar per step)
        if (tid < 16) {
            float f = expf((float)tid * -0.61402269146507890f);  // -ln(10000)/15
            float ang = (float)i * f;
            s->emb[tid] = sinf(ang);
            s->emb[tid + 16] = cosf(ang);
        }
        __syncthreads();

        // time MLP layer 1: t1 = mish(emb @ TW1 + tb1)
        {
            float a = s->tb1[tid];
            #pragma unroll 8
            for (int k = 0; k < TDIM; k++) a += s->emb[k] * s->TW1[k * HID + tid];
            s->t1[tid] = mish_f(a);
        }
        __syncthreads();

        // time MLP layer 2: temb = t1 @ TW2 + tb2 (8-way K-split + reduce)
        {
            int j = tid & 31, p = tid >> 5;
            float a = 0.f;
            const float* tw = s->TW2 + p * 32 * TDIM + j;
            const float* tv = s->t1 + p * 32;
            #pragma unroll 8
            for (int k = 0; k < 32; k++) a += tv[k] * tw[k * TDIM];
            s->tpart[tid] = a;
        }
        __syncthreads();
        if (tid < 32) {
            float a = s->tb2[tid];
            #pragma unroll
            for (int p = 0; p < 8; p++) a += s->tpart[p * 32 + tid];
            s->temb[tid] = a;
        }
        __syncthreads();

        // tcon = temb @ W1[16:48]
        {
            float a = 0.f;
            #pragma unroll 8
            for (int k = 0; k < TDIM; k++) a += s->temb[k] * s->W1t[k * HID + tid];
            s->tcon[tid] = a;
        }
        __syncthreads();

        // layer 1: hA = mish( x @ W1x + S + tcon )
        {
            ULL acc[4][2];
            ulonglong2 tc = *(reinterpret_cast<const ulonglong2*>(s->tcon) + tx);
            #pragma unroll
            for (int r = 0; r < 4; r++) {
                ulonglong2 sv = *(reinterpret_cast<const ulonglong2*>(s->S + (4 * ty + r) * HID) + tx);
                acc[r][0] = add2(sv.x, tc.x);
                acc[r][1] = add2(sv.y, tc.y);
            }
            #pragma unroll
            for (int k = 0; k < ADIM; k++) {
                ulonglong2 w = *(reinterpret_cast<const ulonglong2*>(s->W1x + k * HID) + tx);
                #pragma unroll
                for (int r = 0; r < 4; r++) {
                    ULL a2 = pack2(s->x[(4 * ty + r) * ADIM + k]);
                    acc[r][0] = fma2(a2, w.x, acc[r][0]);
                    acc[r][1] = fma2(a2, w.y, acc[r][1]);
                }
            }
            #pragma unroll
            for (int r = 0; r < 4; r++) {
                float a, b, c, d;
                unpack2(acc[r][0], a, b);
                unpack2(acc[r][1], c, d);
                *reinterpret_cast<float4*>(s->hA + (4 * ty + r) * HS + 4 * tx) =
                    make_float4(mish_f(a), mish_f(b), mish_f(c), mish_f(d));
            }
        }
        __syncthreads();

        gemm_hidden(W2, s->b2, s->hA, s->hB, tx, ty);   // layer 2
        __syncthreads();
        gemm_hidden(W3, s->b3, s->hB, s->hA, tx, ty);   // layer 3
        __syncthreads();

        // layer 4 (eps) + posterior update, one thread per (row, action) element
        {
            float acc = s->b4[uj];
            const float* hr = s->hA + um * HS;
            const float* wr = s->W4T + uj * HS;
            #pragma unroll 8
            for (int k = 0; k < HID; k += 4) {
                float4 h4 = *reinterpret_cast<const float4*>(hr + k);
                float4 w4 = *reinterpret_cast<const float4*>(wr + k);
                acc += h4.x * w4.x + h4.y * w4.y + h4.z * w4.z + h4.w * w4.w;
            }
            float xv = s->x[tid];
            float xr = s->r1[i] * xv - s->r2[i] * acc;
            xr = fminf(fmaxf(xr, -1.f), 1.f);
            float xn = s->c1[i] * xr + s->c2[i] * xv;
            if (i != 0)
                xn += s->stdv[i] * noise[((size_t)sstep * 2048 + row0 + um) * ADIM + uj];
            s->x[tid] = xn;
        }
        __syncthreads();
    }

    float xv = s->x[tid];
    out[(row0 + um) * ADIM + uj] = fminf(fmaxf(xv, -1.f), 1.f);
}

extern "C" void kernel_launch(void* const* d_in, const int* in_sizes, int n_in,
                              void* d_out, int out_size) {
    (void)in_sizes; (void)n_in; (void)out_size;
    cudaFuncSetAttribute(diffusion_kernel,
                         cudaFuncAttributeMaxDynamicSharedMemorySize,
                         (int)sizeof(Smem));
    diffusion_kernel<<<128, 256, sizeof(Smem)>>>(
        (const float*)d_in[0],  // state
        (const float*)d_in[1],  // x_init
        (const float*)d_in[2],  // noise
        (const float*)d_in[3],  // time_W1
        (const float*)d_in[4],  // time_b1
        (const float*)d_in[5],  // time_W2
        (const float*)d_in[6],  // time_b2
        (const float*)d_in[7],  // W1
        (const float*)d_in[8],  // b1
        (const float*)d_in[9],  // W2
        (const float*)d_in[10], // b2
        (const float*)d_in[11], // W3
        (const float*)d_in[12], // b3
        (const float*)d_in[13], // W4
        (const float*)d_in[14], // b4
        (float*)d_out);
}